// round 16
// baseline (speedup 1.0000x reference)
#include <cuda_runtime.h>

// Problem constants
#define BATCH    4096
#define SEQT     512
#define HID      50
#define NBC      32               // batch per CTA
#define NBT      8                // batch per thread
#define NTHREADS 448              // A: warps 0-6 (gt<200), B: warps 7-13 (gt<200)
#define NCTAS    128
#define JP       52               // padded j extent (cols 50,51 zero)
#define JA       28               // A computes Wih1 partial j<JA; B does j>=JA
#define HBS      (JP * NBC)       // floats per h buffer = 1664
#define WMAT     (4 * HID * JP)   // floats per weight matrix = 10400
#define PZ_STRIDE 18              // u64 per thread slot (bank-conflict-free)
#define PZ_U64   (200 * PZ_STRIDE)

typedef unsigned long long u64;

__device__ __forceinline__ void fma2(u64 &acc, u64 a, u64 b) {
    asm("fma.rn.f32x2 %0, %1, %2, %0;" : "+l"(acc) : "l"(a), "l"(b));
}
__device__ __forceinline__ u64 pk2(float a, float b) {
    u64 r;
    unsigned ia = __float_as_uint(a), ib = __float_as_uint(b);
    asm("mov.b64 %0, {%1, %2};" : "=l"(r) : "r"(ia), "r"(ib));
    return r;
}
__device__ __forceinline__ float lo2(u64 v) { return __uint_as_float((unsigned)v); }
__device__ __forceinline__ float hi2(u64 v) { return __uint_as_float((unsigned)(v >> 32)); }

// HW tanh (MUFU)
__device__ __forceinline__ float tanha(float z) {
    float r;
    asm("tanh.approx.f32 %0, %1;" : "=f"(r) : "f"(z));
    return r;
}
// sigmoid with pre-halved argument: sig(2z') = 0.5 + 0.5*tanh(z')
__device__ __forceinline__ float sig_h(float zh) {
    return fmaf(0.5f, tanha(zh), 0.5f);
}

// one j-column of the matmul for 8 batches (4 f32x2 pairs per gate)
__device__ __forceinline__ void gate8(u64* aI, u64* aF, u64* aG, u64* aO,
                                      float wi, float wf, float wg, float wo,
                                      ulonglong2 hA, ulonglong2 hB) {
    u64 pwi = pk2(wi, wi), pwf = pk2(wf, wf), pwg = pk2(wg, wg), pwo = pk2(wo, wo);
    fma2(aI[0], pwi, hA.x); fma2(aI[1], pwi, hA.y); fma2(aI[2], pwi, hB.x); fma2(aI[3], pwi, hB.y);
    fma2(aF[0], pwf, hA.x); fma2(aF[1], pwf, hA.y); fma2(aF[2], pwf, hB.x); fma2(aF[3], pwf, hB.y);
    fma2(aG[0], pwg, hA.x); fma2(aG[1], pwg, hA.y); fma2(aG[2], pwg, hB.x); fma2(aG[3], pwg, hB.y);
    fma2(aO[0], pwo, hA.x); fma2(aO[1], pwo, hA.y); fma2(aO[2], pwo, hB.x); fma2(aO[3], pwo, hB.y);
}

// SMEM: pz[2][PZ_U64] | w0s w1is w1hs (floats) | h0s[3][HBS] h1s[2][HBS] |
//       sb0 sb1 swx (u64[4*HID]) | fcw[52]
#define SMEM_BYTES (2*PZ_U64*8 + 3*WMAT*4 + 5*HBS*4 + 3*4*HID*8 + 52*4)

__global__ __launch_bounds__(NTHREADS, 1)
void lstm_fused_kernel(const float* __restrict__ x,
                       const float* __restrict__ Wih0, const float* __restrict__ Whh0,
                       const float* __restrict__ bih0, const float* __restrict__ bhh0,
                       const float* __restrict__ Wih1, const float* __restrict__ Whh1,
                       const float* __restrict__ bih1, const float* __restrict__ bhh1,
                       const float* __restrict__ fcw_g, const float* __restrict__ fcb_g,
                       float* __restrict__ out)
{
    extern __shared__ u64 smu[];
    u64*   pz   = smu;                        // [2][PZ_U64]
    float* w0s  = (float*)(pz + 2 * PZ_U64);  // layer0 Whh   [4H][JP]
    float* w1is = w0s  + WMAT;                // layer1 Wih
    float* w1hs = w1is + WMAT;                // layer1 Whh
    float* h0s  = w1hs + WMAT;                // [3][JP][NBC]
    float* h1s  = h0s  + 3 * HBS;             // [2][JP][NBC]
    u64*   sb0  = (u64*)(h1s + 2 * HBS);      // [4*HID] (b,b) pairs
    u64*   sb1  = sb0 + 4 * HID;
    u64*   swx  = sb1 + 4 * HID;
    float* fcws = (float*)(swx + 4 * HID);    // [0:50) w, [50] bias

    const int tid = threadIdx.x;

    // ---- stage weights; sigmoid-gate rows (g = 0,1,3) pre-scaled by 0.5 ----
    for (int idx = tid; idx < WMAT; idx += NTHREADS) {
        int row = idx / JP, col = idx - row * JP;
        int g = row / HID;
        float sc = (g == 2) ? 1.0f : 0.5f;
        float a = 0.f, b = 0.f, c = 0.f;
        if (col < HID) {
            a = sc * Whh0[row * HID + col];
            b = sc * Wih1[row * HID + col];
            c = sc * Whh1[row * HID + col];
        }
        w0s[idx]  = a;
        w1is[idx] = b;
        w1hs[idx] = c;
    }
    for (int idx = tid; idx < 5 * HBS; idx += NTHREADS)
        h0s[idx] = 0.0f;                      // zeros h0[3] and h1[2]
    if (tid < HID) {
        int u = tid;
        #pragma unroll
        for (int g = 0; g < 4; g++) {
            float sc = (g == 2) ? 1.0f : 0.5f;
            float b0v = sc * (bih0[g * HID + u] + bhh0[g * HID + u]);
            float b1v = sc * (bih1[g * HID + u] + bhh1[g * HID + u]);
            float wxv = sc * Wih0[g * HID + u];     // IN = 1
            sb0[g * HID + u] = pk2(b0v, b0v);
            sb1[g * HID + u] = pk2(b1v, b1v);
            swx[g * HID + u] = pk2(wxv, wxv);
        }
        fcws[u] = fcw_g[u];
    }
    if (tid == 0) fcws[HID] = fcb_g[0];

    // ---- group / lane mapping (warp-aligned groups) ----
    const bool isA = (tid < 200);                 // warps 0-6 (lanes 200-223 idle)
    const bool isB = (tid >= 224 && tid < 424);   // warps 7-13 (lanes 424-447 idle)
    const int  gt  = isA ? tid : (isB ? (tid - 224) : 0);
    const int  bg  = gt & 3;          // batch group (fast in warp)
    const int  u   = gt >> 2;         // hidden unit 0..49
    const int  bb  = bg * NBT;        // local batch base (floats)

    float cst[NBT] = {0.f,0.f,0.f,0.f,0.f,0.f,0.f,0.f};   // c0 for A, c1 for B

    const float* xp = x + (size_t)(blockIdx.x * NBC + bb) * SEQT;
    float xv[NBT];
    if (isA) {
        #pragma unroll
        for (int nb = 0; nb < NBT; nb++) xv[nb] = xp[nb * SEQT + 0];
    }

    __syncthreads();

    for (int s = 0; s <= SEQT + 1; s++) {
        const int m_w  = s % 3;            // h0 write buffer   (h0(s))
        const int m_r1 = (s + 2) % 3;      // h0(s-1)
        const int m_r2 = (s + 1) % 3;      // h0(s-2)

        if (isA) {
            // partial accumulators: partialA(t = s-1) = b1 + Wih1[:,0:JA] @ h0(s-1)
            u64 pI[4], pF[4], pG[4], pO[4];
            if (s <= SEQT) {
                u64 b1I = sb1[0*HID+u], b1F = sb1[1*HID+u], b1G = sb1[2*HID+u], b1O = sb1[3*HID+u];
                #pragma unroll
                for (int p = 0; p < 4; p++) { pI[p] = b1I; pF[p] = b1F; pG[p] = b1G; pO[p] = b1O; }
            }
            if (s < SEQT) {
                // ===== layer 0, t = s  (merged with partial: shared h0(s-1) loads) =====
                u64 aI[4], aF[4], aG[4], aO[4];
                {
                    u64 xx[4] = {pk2(xv[0], xv[1]), pk2(xv[2], xv[3]),
                                 pk2(xv[4], xv[5]), pk2(xv[6], xv[7])};
                    u64 bI = sb0[0*HID+u], bF = sb0[1*HID+u], bG = sb0[2*HID+u], bO = sb0[3*HID+u];
                    u64 wI = swx[0*HID+u], wF = swx[1*HID+u], wG = swx[2*HID+u], wO = swx[3*HID+u];
                    #pragma unroll
                    for (int p = 0; p < 4; p++) {
                        aI[p] = bI; fma2(aI[p], wI, xx[p]);
                        aF[p] = bF; fma2(aF[p], wF, xx[p]);
                        aG[p] = bG; fma2(aG[p], wG, xx[p]);
                        aO[p] = bO; fma2(aO[p], wO, xx[p]);
                    }
                }
                {
                    const float* w0r0 = w0s + (0 * HID + u) * JP;
                    const float* w0r1 = w0s + (1 * HID + u) * JP;
                    const float* w0r2 = w0s + (2 * HID + u) * JP;
                    const float* w0r3 = w0s + (3 * HID + u) * JP;
                    const float* wi0  = w1is + (0 * HID + u) * JP;
                    const float* wi1  = w1is + (1 * HID + u) * JP;
                    const float* wi2  = w1is + (2 * HID + u) * JP;
                    const float* wi3  = w1is + (3 * HID + u) * JP;
                    const float* hp   = h0s + m_r1 * HBS + bb;
                    for (int j4 = 0; j4 < JP; j4 += 4) {
                        const float* hj = hp + j4 * NBC;
                        ulonglong2 hA0 = *(const ulonglong2*)(hj);
                        ulonglong2 hB0 = *(const ulonglong2*)(hj + 4);
                        ulonglong2 hA1 = *(const ulonglong2*)(hj + NBC);
                        ulonglong2 hB1 = *(const ulonglong2*)(hj + NBC + 4);
                        ulonglong2 hA2 = *(const ulonglong2*)(hj + 2*NBC);
                        ulonglong2 hB2 = *(const ulonglong2*)(hj + 2*NBC + 4);
                        ulonglong2 hA3 = *(const ulonglong2*)(hj + 3*NBC);
                        ulonglong2 hB3 = *(const ulonglong2*)(hj + 3*NBC + 4);
                        {
                            float4 wi = *(const float4*)(w0r0 + j4);
                            float4 wf = *(const float4*)(w0r1 + j4);
                            float4 wg = *(const float4*)(w0r2 + j4);
                            float4 wo = *(const float4*)(w0r3 + j4);
                            gate8(aI, aF, aG, aO, wi.x, wf.x, wg.x, wo.x, hA0, hB0);
                            gate8(aI, aF, aG, aO, wi.y, wf.y, wg.y, wo.y, hA1, hB1);
                            gate8(aI, aF, aG, aO, wi.z, wf.z, wg.z, wo.z, hA2, hB2);
                            gate8(aI, aF, aG, aO, wi.w, wf.w, wg.w, wo.w, hA3, hB3);
                        }
                        if (j4 < JA) {   // shared h loads feed the partial too
                            float4 vi = *(const float4*)(wi0 + j4);
                            float4 vf = *(const float4*)(wi1 + j4);
                            float4 vg = *(const float4*)(wi2 + j4);
                            float4 vo = *(const float4*)(wi3 + j4);
                            gate8(pI, pF, pG, pO, vi.x, vf.x, vg.x, vo.x, hA0, hB0);
                            gate8(pI, pF, pG, pO, vi.y, vf.y, vg.y, vo.y, hA1, hB1);
                            gate8(pI, pF, pG, pO, vi.z, vf.z, vg.z, vo.z, hA2, hB2);
                            gate8(pI, pF, pG, pO, vi.w, vf.w, vg.w, vo.w, hA3, hB3);
                        }
                    }
                }
                {
                    float gi[8] = {lo2(aI[0]),hi2(aI[0]),lo2(aI[1]),hi2(aI[1]),lo2(aI[2]),hi2(aI[2]),lo2(aI[3]),hi2(aI[3])};
                    float gf[8] = {lo2(aF[0]),hi2(aF[0]),lo2(aF[1]),hi2(aF[1]),lo2(aF[2]),hi2(aF[2]),lo2(aF[3]),hi2(aF[3])};
                    float gz[8] = {lo2(aG[0]),hi2(aG[0]),lo2(aG[1]),hi2(aG[1]),lo2(aG[2]),hi2(aG[2]),lo2(aG[3]),hi2(aG[3])};
                    float go[8] = {lo2(aO[0]),hi2(aO[0]),lo2(aO[1]),hi2(aO[1]),lo2(aO[2]),hi2(aO[2]),lo2(aO[3]),hi2(aO[3])};
                    float hn[8];
                    #pragma unroll
                    for (int nb = 0; nb < NBT; nb++) {
                        float ig = sig_h(gi[nb]);
                        float fg = sig_h(gf[nb]);
                        float zg = tanha(gz[nb]);
                        float og = sig_h(go[nb]);
                        cst[nb] = fg * cst[nb] + ig * zg;
                        hn[nb] = og * tanha(cst[nb]);
                    }
                    float* hw = h0s + m_w * HBS + u * NBC + bb;
                    *(float4*)(hw)     = make_float4(hn[0], hn[1], hn[2], hn[3]);
                    *(float4*)(hw + 4) = make_float4(hn[4], hn[5], hn[6], hn[7]);
                }
                // next-step x load (after the hot loop: keeps regs low in the loop)
                {
                    const int tn = (s + 1 < SEQT) ? s + 1 : s;
                    #pragma unroll
                    for (int nb = 0; nb < NBT; nb++) xv[nb] = xp[nb * SEQT + tn];
                }
            } else if (s == SEQT) {
                // drain step: partial only (no L0)
                const float* wi0 = w1is + (0 * HID + u) * JP;
                const float* wi1 = w1is + (1 * HID + u) * JP;
                const float* wi2 = w1is + (2 * HID + u) * JP;
                const float* wi3 = w1is + (3 * HID + u) * JP;
                const float* hp  = h0s + m_r1 * HBS + bb;
                for (int j4 = 0; j4 < JA; j4 += 4) {
                    const float* hj = hp + j4 * NBC;
                    float4 vi = *(const float4*)(wi0 + j4);
                    float4 vf = *(const float4*)(wi1 + j4);
                    float4 vg = *(const float4*)(wi2 + j4);
                    float4 vo = *(const float4*)(wi3 + j4);
                    ulonglong2 hA, hB;
                    hA = *(const ulonglong2*)(hj);           hB = *(const ulonglong2*)(hj + 4);
                    gate8(pI, pF, pG, pO, vi.x, vf.x, vg.x, vo.x, hA, hB);
                    hA = *(const ulonglong2*)(hj + NBC);     hB = *(const ulonglong2*)(hj + NBC + 4);
                    gate8(pI, pF, pG, pO, vi.y, vf.y, vg.y, vo.y, hA, hB);
                    hA = *(const ulonglong2*)(hj + 2*NBC);   hB = *(const ulonglong2*)(hj + 2*NBC + 4);
                    gate8(pI, pF, pG, pO, vi.z, vf.z, vg.z, vo.z, hA, hB);
                    hA = *(const ulonglong2*)(hj + 3*NBC);   hB = *(const ulonglong2*)(hj + 3*NBC + 4);
                    gate8(pI, pF, pG, pO, vi.w, vf.w, vg.w, vo.w, hA, hB);
                }
            }
            if (s <= SEQT) {
                u64* pzw = pz + (s & 1) * PZ_U64 + gt * PZ_STRIDE;
                *(ulonglong2*)(pzw + 0)  = make_ulonglong2(pI[0], pI[1]);
                *(ulonglong2*)(pzw + 2)  = make_ulonglong2(pI[2], pI[3]);
                *(ulonglong2*)(pzw + 4)  = make_ulonglong2(pF[0], pF[1]);
                *(ulonglong2*)(pzw + 6)  = make_ulonglong2(pF[2], pF[3]);
                *(ulonglong2*)(pzw + 8)  = make_ulonglong2(pG[0], pG[1]);
                *(ulonglong2*)(pzw + 10) = make_ulonglong2(pG[2], pG[3]);
                *(ulonglong2*)(pzw + 12) = make_ulonglong2(pO[0], pO[1]);
                *(ulonglong2*)(pzw + 14) = make_ulonglong2(pO[2], pO[3]);
            }
        } else if (isB) {
            if (s >= 2) {
                // ===== layer 1, t = s-2 =====
                u64 aI[4], aF[4], aG[4], aO[4];
                {
                    const u64* pzr = pz + ((s + 1) & 1) * PZ_U64 + gt * PZ_STRIDE;
                    ulonglong2 q0 = *(const ulonglong2*)(pzr + 0);
                    ulonglong2 q1 = *(const ulonglong2*)(pzr + 2);
                    ulonglong2 q2 = *(const ulonglong2*)(pzr + 4);
                    ulonglong2 q3 = *(const ulonglong2*)(pzr + 6);
                    ulonglong2 q4 = *(const ulonglong2*)(pzr + 8);
                    ulonglong2 q5 = *(const ulonglong2*)(pzr + 10);
                    ulonglong2 q6 = *(const ulonglong2*)(pzr + 12);
                    ulonglong2 q7 = *(const ulonglong2*)(pzr + 14);
                    aI[0] = q0.x; aI[1] = q0.y; aI[2] = q1.x; aI[3] = q1.y;
                    aF[0] = q2.x; aF[1] = q2.y; aF[2] = q3.x; aF[3] = q3.y;
                    aG[0] = q4.x; aG[1] = q4.y; aG[2] = q5.x; aG[3] = q5.y;
                    aO[0] = q6.x; aO[1] = q6.y; aO[2] = q7.x; aO[3] = q7.y;
                }
                {
                    // Whh1 @ h1(t-1), full JP
                    const float* wr0 = w1hs + (0 * HID + u) * JP;
                    const float* wr1 = w1hs + (1 * HID + u) * JP;
                    const float* wr2 = w1hs + (2 * HID + u) * JP;
                    const float* wr3 = w1hs + (3 * HID + u) * JP;
                    const float* hp  = h1s + ((s + 1) & 1) * HBS + bb;   // h1(t-1)
                    for (int j4 = 0; j4 < JP; j4 += 4) {
                        float4 wi = *(const float4*)(wr0 + j4);
                        float4 wf = *(const float4*)(wr1 + j4);
                        float4 wg = *(const float4*)(wr2 + j4);
                        float4 wo = *(const float4*)(wr3 + j4);
                        const float* hj = hp + j4 * NBC;
                        ulonglong2 hA, hB;
                        hA = *(const ulonglong2*)(hj);           hB = *(const ulonglong2*)(hj + 4);
                        gate8(aI, aF, aG, aO, wi.x, wf.x, wg.x, wo.x, hA, hB);
                        hA = *(const ulonglong2*)(hj + NBC);     hB = *(const ulonglong2*)(hj + NBC + 4);
                        gate8(aI, aF, aG, aO, wi.y, wf.y, wg.y, wo.y, hA, hB);
                        hA = *(const ulonglong2*)(hj + 2*NBC);   hB = *(const ulonglong2*)(hj + 2*NBC + 4);
                        gate8(aI, aF, aG, aO, wi.z, wf.z, wg.z, wo.z, hA, hB);
                        hA = *(const ulonglong2*)(hj + 3*NBC);   hB = *(const ulonglong2*)(hj + 3*NBC + 4);
                        gate8(aI, aF, aG, aO, wi.w, wf.w, wg.w, wo.w, hA, hB);
                    }
                }
                {
                    // Wih1[:, JA:] @ h0(t)
                    const float* wr0 = w1is + (0 * HID + u) * JP;
                    const float* wr1 = w1is + (1 * HID + u) * JP;
                    const float* wr2 = w1is + (2 * HID + u) * JP;
                    const float* wr3 = w1is + (3 * HID + u) * JP;
                    const float* hp  = h0s + m_r2 * HBS + bb;            // h0(t = s-2)
                    for (int j4 = JA; j4 < JP; j4 += 4) {
                        float4 wi = *(const float4*)(wr0 + j4);
                        float4 wf = *(const float4*)(wr1 + j4);
                        float4 wg = *(const float4*)(wr2 + j4);
                        float4 wo = *(const float4*)(wr3 + j4);
                        const float* hj = hp + j4 * NBC;
                        ulonglong2 hA, hB;
                        hA = *(const ulonglong2*)(hj);           hB = *(const ulonglong2*)(hj + 4);
                        gate8(aI, aF, aG, aO, wi.x, wf.x, wg.x, wo.x, hA, hB);
                        hA = *(const ulonglong2*)(hj + NBC);     hB = *(const ulonglong2*)(hj + NBC + 4);
                        gate8(aI, aF, aG, aO, wi.y, wf.y, wg.y, wo.y, hA, hB);
                        hA = *(const ulonglong2*)(hj + 2*NBC);   hB = *(const ulonglong2*)(hj + 2*NBC + 4);
                        gate8(aI, aF, aG, aO, wi.z, wf.z, wg.z, wo.z, hA, hB);
                        hA = *(const ulonglong2*)(hj + 3*NBC);   hB = *(const ulonglong2*)(hj + 3*NBC + 4);
                        gate8(aI, aF, aG, aO, wi.w, wf.w, wg.w, wo.w, hA, hB);
                    }
                }
                {
                    float gi[8] = {lo2(aI[0]),hi2(aI[0]),lo2(aI[1]),hi2(aI[1]),lo2(aI[2]),hi2(aI[2]),lo2(aI[3]),hi2(aI[3])};
                    float gf[8] = {lo2(aF[0]),hi2(aF[0]),lo2(aF[1]),hi2(aF[1]),lo2(aF[2]),hi2(aF[2]),lo2(aF[3]),hi2(aF[3])};
                    float gz[8] = {lo2(aG[0]),hi2(aG[0]),lo2(aG[1]),hi2(aG[1]),lo2(aG[2]),hi2(aG[2]),lo2(aG[3]),hi2(aG[3])};
                    float go[8] = {lo2(aO[0]),hi2(aO[0]),lo2(aO[1]),hi2(aO[1]),lo2(aO[2]),hi2(aO[2]),lo2(aO[3]),hi2(aO[3])};
                    float hn[8];
                    #pragma unroll
                    for (int nb = 0; nb < NBT; nb++) {
                        float ig = sig_h(gi[nb]);
                        float fg = sig_h(gf[nb]);
                        float zg = tanha(gz[nb]);
                        float og = sig_h(go[nb]);
                        cst[nb] = fg * cst[nb] + ig * zg;
                        hn[nb] = og * tanha(cst[nb]);
                    }
                    float* hw = h1s + (s & 1) * HBS + u * NBC + bb;
                    *(float4*)(hw)     = make_float4(hn[0], hn[1], hn[2], hn[3]);
                    *(float4*)(hw + 4) = make_float4(hn[4], hn[5], hn[6], hn[7]);
                }
            }
        }
        __syncthreads();
    }

    // ===== final projection: out[b] = h1(T-1)[:, b] . fcw + fcb =====
    // h1(511) written at s=513 into parity 1 -> buffer 1
    if (tid < NBC) {
        float acc = fcws[HID];
        const float* hf = h1s + HBS;
        #pragma unroll 10
        for (int uu = 0; uu < HID; uu++)
            acc += hf[uu * NBC + tid] * fcws[uu];
        out[blockIdx.x * NBC + tid] = acc;
    }
}

extern "C" void kernel_launch(void* const* d_in, const int* in_sizes, int n_in,
                              void* d_out, int out_size)
{
    const float* x    = (const float*)d_in[0];
    const float* Wih0 = (const float*)d_in[1];
    const float* Whh0 = (const float*)d_in[2];
    const float* bih0 = (const float*)d_in[3];
    const float* bhh0 = (const float*)d_in[4];
    const float* Wih1 = (const float*)d_in[5];
    const float* Whh1 = (const float*)d_in[6];
    const float* bih1 = (const float*)d_in[7];
    const float* bhh1 = (const float*)d_in[8];
    const float* fcw  = (const float*)d_in[9];
    const float* fcb  = (const float*)d_in[10];
    float* out = (float*)d_out;

    cudaFuncSetAttribute(lstm_fused_kernel,
                         cudaFuncAttributeMaxDynamicSharedMemorySize, SMEM_BYTES);
    lstm_fused_kernel<<<NCTAS, NTHREADS, SMEM_BYTES>>>(
        x, Wih0, Whh0, bih0, bhh0, Wih1, Whh1, bih1, bhh1, fcw, fcb, out);
}